// round 12
// baseline (speedup 1.0000x reference)
#include <cuda_runtime.h>
#include <cuda_bf16.h>
#include <cuda_fp16.h>
#include <cstdint>

// ======================= problem constants =======================
static constexpr int Q    = 2048;
static constexpr int S    = 8;
static constexpr int D    = 2048;
static constexpr int SP   = 100;
static constexpr int NCLS = 20;
static constexpr int MR = Q * S;    // 16384 target frames
static constexpr int NR = SP * S;   // 800 support frames

// GEMM tiling (fp8: 1 byte/elem)
static constexpr int BM = 64;
static constexpr int BN = 160;          // 800 = 5 * 160
static constexpr int BK = 128;          // 128 fp8 = 128B row (swizzle atom)
static constexpr int NCHUNK = D / BK;   // 16
static constexpr int NTHREADS = 256;    // 8 warps: 2 over M x 4 over N

static constexpr int STAGE_A = BM * 128;   // 8192 B
static constexpr int STAGE_B = BN * 128;   // 20480 B
static constexpr int PIPE_BYTES = 2 * STAGE_A + 2 * STAGE_B;   // 57344

// epilogue dist tile in smem: [BM][DSTR] floats
static constexpr int DSTR = 164;           // 160 + pad
static constexpr int DIST_BYTES = BM * DSTR * 4;               // 41984
static constexpr int SM_BYTES = (DIST_BYTES > PIPE_BYTES) ? DIST_BYTES : PIPE_BYTES;  // 57344

// ======================= device scratch =======================
__device__ uint8_t g_A[(size_t)MR * D];            // 32 MB e4m3
__device__ uint8_t g_B[(size_t)NR * D];            // 1.6 MB e4m3
__device__ float g_normT[MR];
__device__ float g_normS[NR];

// ======================= asm helpers (generic-target safe) =======================
__device__ __forceinline__ uint32_t smem_to_u32(const void* smem_ptr) {
    uint32_t addr;
    asm("{ .reg .u64 tmp; cvta.to.shared.u64 tmp, %1; cvt.u32.u64 %0, tmp; }"
        : "=r"(addr) : "l"(smem_ptr));
    return addr;
}

__device__ __forceinline__ void cp_async16(uint32_t dst, const void* src) {
    asm volatile("cp.async.cg.shared.global [%0], [%1], 16;" :: "r"(dst), "l"(src));
}
__device__ __forceinline__ void cp_commit() {
    asm volatile("cp.async.commit_group;");
}
template <int N>
__device__ __forceinline__ void cp_wait() {
    asm volatile("cp.async.wait_group %0;" :: "n"(N));
}

__device__ __forceinline__ void ldsm_x4(uint32_t r[4], uint32_t addr) {
    asm volatile("ldmatrix.sync.aligned.m8n8.x4.shared.b16 {%0,%1,%2,%3}, [%4];"
        : "=r"(r[0]), "=r"(r[1]), "=r"(r[2]), "=r"(r[3]) : "r"(addr));
}
__device__ __forceinline__ void ldsm_x2(uint32_t r[2], uint32_t addr) {
    asm volatile("ldmatrix.sync.aligned.m8n8.x2.shared.b16 {%0,%1}, [%2];"
        : "=r"(r[0]), "=r"(r[1]) : "r"(addr));
}
// fp8 e4m3 MMA with f16 accumulator
__device__ __forceinline__ void mma16832_fp8_f16(uint32_t c[2], const uint32_t a[4], const uint32_t b[2]) {
    asm volatile(
        "mma.sync.aligned.m16n8k32.row.col.f16.e4m3.e4m3.f16 "
        "{%0,%1}, {%2,%3,%4,%5}, {%6,%7}, {%0,%1};"
        : "+r"(c[0]), "+r"(c[1])
        : "r"(a[0]), "r"(a[1]), "r"(a[2]), "r"(a[3]), "r"(b[0]), "r"(b[1]));
}

// ======================= kernel 1: fp32 -> e4m3 + row norms (A and B fused) ==========
__global__ void __launch_bounds__(256) convert_norm_kernel(const float* __restrict__ srcA,
                                                           const float* __restrict__ srcB) {
    const int blk = blockIdx.x;
    const bool isB = blk >= MR;
    const int row = isB ? blk - MR : blk;
    const float* src = isB ? srcB : srcA;
    uint8_t* dst = isB ? g_B : g_A;
    float* norms = isB ? g_normS : g_normT;

    const float4* s = reinterpret_cast<const float4*>(src) + (size_t)row * (D / 4);
    uint32_t* d = reinterpret_cast<uint32_t*>(dst) + (size_t)row * (D / 4);

    float ss = 0.f;
    for (int i = threadIdx.x; i < D / 4; i += blockDim.x) {
        float4 v = s[i];
        ss = fmaf(v.x, v.x, fmaf(v.y, v.y, fmaf(v.z, v.z, fmaf(v.w, v.w, ss))));
        uint16_t lo, hi;  // e4m3x2: second f32 operand lands in byte0
        asm("cvt.rn.satfinite.e4m3x2.f32 %0, %1, %2;" : "=h"(lo) : "f"(v.y), "f"(v.x));
        asm("cvt.rn.satfinite.e4m3x2.f32 %0, %1, %2;" : "=h"(hi) : "f"(v.w), "f"(v.z));
        d[i] = (uint32_t)lo | ((uint32_t)hi << 16);
    }
    for (int o = 16; o > 0; o >>= 1) ss += __shfl_down_sync(0xFFFFFFFFu, ss, o);
    __shared__ float ws[8];
    if ((threadIdx.x & 31) == 0) ws[threadIdx.x >> 5] = ss;
    __syncthreads();
    if (threadIdx.x == 0) {
        float t = 0.f;
        #pragma unroll
        for (int w = 0; w < 8; w++) t += ws[w];
        norms[row] = sqrtf(t);
    }
}

// ======================= OTAM softmin helpers =======================
__device__ __forceinline__ float softmin2(float a, float b) {
    float m = fminf(a, b);
    float x = fabsf(a - b);
    return m - 0.1f * __logf(1.0f + __expf(-x * 10.0f));
}
__device__ __forceinline__ float softmin3(float a, float b, float c) {
    float m = fminf(fminf(a, b), c);
    float s = __expf((m - a) * 10.0f) + __expf((m - b) * 10.0f) + __expf((m - c) * 10.0f);
    return m - 0.1f * __logf(s);
}

// DP over an 8x8 dist block read from smem. TR swaps indices.
template <bool TR>
__device__ __forceinline__ float otam_dp_smem(const float* __restrict__ ds) {
    auto at = [&](int i, int j) -> float {
        return TR ? ds[j * DSTR + i] : ds[i * DSTR + j];
    };
    float prev[10], cur[10];
    prev[0] = 0.f;
    float run = 0.f;
    #pragma unroll
    for (int s = 0; s < 8; s++) {
        run += at(0, s);
        prev[s + 1] = run;
    }
    prev[9] = run;
    #pragma unroll
    for (int ll = 1; ll < 8; ll++) {
        cur[0] = 0.f;
        cur[1] = at(ll, 0) + softmin3(prev[0], prev[1], cur[0]);
        #pragma unroll
        for (int m = 2; m <= 8; m++)
            cur[m] = at(ll, m - 1) + softmin2(prev[m - 1], cur[m - 1]);
        cur[9] = softmin3(prev[8], prev[9], cur[8]);
        #pragma unroll
        for (int m = 0; m < 10; m++) prev[m] = cur[m];
    }
    return prev[9];
}

// ======================= kernel 2: FP8 GEMM + dist + OTAM DP + class-mean =============
__device__ __forceinline__ void load_stage(uint32_t sb, int buf, int kc, int m0, int n0, int t) {
    uint32_t a_s = sb + buf * STAGE_A;
    uint32_t b_s = sb + 2 * STAGE_A + buf * STAGE_B;
    const uint8_t* gA = g_A + (size_t)m0 * D + kc * BK;
    const uint8_t* gB = g_B + (size_t)n0 * D + kc * BK;
    #pragma unroll
    for (int i = 0; i < (BM * 8) / NTHREADS; i++) {      // 2
        int idx = i * NTHREADS + t;
        int r = idx >> 3, c = idx & 7;
        cp_async16(a_s + r * 128 + (((uint32_t)(c ^ (r & 7))) << 4),
                   gA + (size_t)r * D + c * 16);
    }
    #pragma unroll
    for (int i = 0; i < (BN * 8) / NTHREADS; i++) {      // 5
        int idx = i * NTHREADS + t;
        int r = idx >> 3, c = idx & 7;
        cp_async16(b_s + r * 128 + (((uint32_t)(c ^ (r & 7))) << 4),
                   gB + (size_t)r * D + c * 16);
    }
    cp_commit();
}

__global__ void __launch_bounds__(NTHREADS, 3) gemm_dp_kernel(const int* __restrict__ labels,
                                                              float* __restrict__ out) {
    extern __shared__ char smem[];
    const uint32_t sb = smem_to_u32(smem);
    float* dist_s = reinterpret_cast<float*>(smem);
    __shared__ int lab_s[SP];
    __shared__ float w_s[SP];
    const int t = threadIdx.x;
    const int l = t & 31;
    const int wid = t >> 5;
    const int wm = wid & 1;        // 2 warps over M (32 rows each)
    const int wn = wid >> 1;       // 4 warps over N (40 cols each)
    const int n0 = blockIdx.x * BN;
    const int m0 = blockIdx.y * BM;

    uint32_t acc[2][5][2];         // f16x2 accumulators, warp tile 32x40
    #pragma unroll
    for (int mt = 0; mt < 2; mt++)
        #pragma unroll
        for (int nt = 0; nt < 5; nt++) {
            acc[mt][nt][0] = 0u;
            acc[mt][nt][1] = 0u;
        }

    load_stage(sb, 0, 0, m0, n0, t);
    if (t < SP) lab_s[t] = labels[t];

    const int la = l & 15;
    const int sa = l & 7;
    const int a_hi = l >> 4;
    const int b_hi = (l >> 3) & 1;
    const uint32_t a_row_off = (uint32_t)(wm * 32 + la) * 128;
    const uint32_t b_row_off = (uint32_t)(wn * 40 + (l & 7)) * 128;

    int buf = 0;
    #pragma unroll 1
    for (int c = 0; c < NCHUNK; c++) {
        if (c + 1 < NCHUNK) {
            load_stage(sb, buf ^ 1, c + 1, m0, n0, t);
            cp_wait<1>();
        } else {
            cp_wait<0>();
        }
        __syncthreads();

        const uint32_t a_s = sb + buf * STAGE_A;
        const uint32_t b_s = sb + 2 * STAGE_A + buf * STAGE_B;

        #pragma unroll
        for (int ks = 0; ks < BK / 32; ks++) {   // 4 k-steps of 32 fp8
            uint32_t afr[2][4], bfr[5][2];
            #pragma unroll
            for (int mt = 0; mt < 2; mt++)
                ldsm_x4(afr[mt], a_s + a_row_off + (uint32_t)(mt * 16 * 128)
                                 + (((uint32_t)((ks * 2 + a_hi) ^ sa)) << 4));
            #pragma unroll
            for (int nt = 0; nt < 5; nt++)
                ldsm_x2(bfr[nt], b_s + b_row_off + (uint32_t)(nt * 8 * 128)
                                 + (((uint32_t)((ks * 2 + b_hi) ^ sa)) << 4));
            #pragma unroll
            for (int mt = 0; mt < 2; mt++)
                #pragma unroll
                for (int nt = 0; nt < 5; nt++)
                    mma16832_fp8_f16(acc[mt][nt], afr[mt], bfr[nt]);
        }
        __syncthreads();
        buf ^= 1;
    }

    // ---- epilogue A: dist = 1 - dot/(|t||s|+eps) into smem tile ----
    const int grp = l >> 2;
    const int tid4 = l & 3;
    #pragma unroll
    for (int mt = 0; mt < 2; mt++) {
        const int lm0 = wm * 32 + mt * 16 + grp;       // local row in [0,64)
        const float nT0 = g_normT[m0 + lm0];
        const float nT1 = g_normT[m0 + lm0 + 8];
        #pragma unroll
        for (int nt = 0; nt < 5; nt++) {
            const int ln = wn * 40 + nt * 8 + tid4 * 2;  // local col in [0,160)
            const float nS0 = g_normS[n0 + ln];
            const float nS1 = g_normS[n0 + ln + 1];
            float2 lo = __half22float2(*reinterpret_cast<const __half2*>(&acc[mt][nt][0]));
            float2 hi = __half22float2(*reinterpret_cast<const __half2*>(&acc[mt][nt][1]));
            dist_s[lm0 * DSTR + ln]           = 1.f - lo.x / (nT0 * nS0 + 0.01f);
            dist_s[lm0 * DSTR + ln + 1]       = 1.f - lo.y / (nT0 * nS1 + 0.01f);
            dist_s[(lm0 + 8) * DSTR + ln]     = 1.f - hi.x / (nT1 * nS0 + 0.01f);
            dist_s[(lm0 + 8) * DSTR + ln + 1] = 1.f - hi.y / (nT1 * nS1 + 0.01f);
        }
    }
    __syncthreads();

    // per-sp weight = 1/count(label[sp]) (labels already in smem)
    if (t < SP) {
        const int c = lab_s[t];
        int n = 0;
        #pragma unroll 4
        for (int i = 0; i < SP; i++) n += (lab_s[i] == c) ? 1 : 0;
        w_s[t] = 1.f / (float)n;
    }
    __syncthreads();

    // ---- epilogue B: OTAM DP on 8 q-blocks x 20 sp-blocks, fold into class means ----
    const int q0 = m0 >> 3;
    const int sp0 = n0 >> 3;
    if (t < 160) {
        const int lq = t & 7;
        const int lsp = t >> 3;
        const int sp = sp0 + lsp;
        const float* ds = dist_s + (lq * 8) * DSTR + lsp * 8;
        float v = otam_dp_smem<false>(ds) + otam_dp_smem<true>(ds);
        atomicAdd(out + (size_t)(q0 + lq) * NCLS + lab_s[sp], -v * w_s[sp]);
    }
}

// ======================= launch =======================
extern "C" void kernel_launch(void* const* d_in, const int* in_sizes, int n_in,
                              void* d_out, int out_size) {
    const float* tf = (const float*)d_in[0];      // [2048, 8, 2048]
    const float* sf = (const float*)d_in[1];      // [100, 8, 2048]
    const int* labels = (const int*)d_in[2];      // [100]
    float* out = (float*)d_out;                   // [1, 2048, 20]
    (void)in_sizes; (void)n_in;

    cudaFuncSetAttribute(gemm_dp_kernel,
                         cudaFuncAttributeMaxDynamicSharedMemorySize, SM_BYTES);

    cudaMemsetAsync(out, 0, (size_t)out_size * sizeof(float));
    convert_norm_kernel<<<MR + NR, 256>>>(tf, sf);
    gemm_dp_kernel<<<dim3(NR / BN, MR / BM), NTHREADS, SM_BYTES>>>(labels, out);
}

// round 13
// speedup vs baseline: 1.0551x; 1.0551x over previous
#include <cuda_runtime.h>
#include <cuda_bf16.h>
#include <cuda_fp16.h>
#include <cstdint>

// ======================= problem constants =======================
static constexpr int Q    = 2048;
static constexpr int S    = 8;
static constexpr int D    = 2048;
static constexpr int SP   = 100;
static constexpr int NCLS = 20;
static constexpr int MR = Q * S;    // 16384 target frames
static constexpr int NR = SP * S;   // 800 support frames

// GEMM tiling (fp8: 1 byte/elem)
static constexpr int BM = 64;
static constexpr int BN = 160;          // 800 = 5 * 160
static constexpr int BK = 128;          // 128 fp8 = 128B row (swizzle atom)
static constexpr int NCHUNK = D / BK;   // 16
static constexpr int NTHREADS = 256;    // 8 warps: 2 over M x 4 over N

static constexpr int STAGE_A = BM * 128;   // 8192 B
static constexpr int STAGE_B = BN * 128;   // 20480 B
static constexpr int PIPE_BYTES = 2 * STAGE_A + 2 * STAGE_B;   // 57344

// epilogue dist tile in smem: [BM][DSTR] floats
static constexpr int DSTR = 164;           // 160 + pad
static constexpr int DIST_BYTES = BM * DSTR * 4;               // 41984
static constexpr int SM_BYTES = (DIST_BYTES > PIPE_BYTES) ? DIST_BYTES : PIPE_BYTES;  // 57344

// ======================= device scratch =======================
__device__ uint8_t g_A[(size_t)MR * D];            // 32 MB e4m3
__device__ uint8_t g_B[(size_t)NR * D];            // 1.6 MB e4m3
__device__ float g_normT[MR];
__device__ float g_normS[NR];
__device__ float g_cum[(size_t)Q * SP];            // [q][sp]

// ======================= asm helpers (generic-target safe) =======================
__device__ __forceinline__ uint32_t smem_to_u32(const void* smem_ptr) {
    uint32_t addr;
    asm("{ .reg .u64 tmp; cvta.to.shared.u64 tmp, %1; cvt.u32.u64 %0, tmp; }"
        : "=r"(addr) : "l"(smem_ptr));
    return addr;
}

__device__ __forceinline__ void cp_async16(uint32_t dst, const void* src) {
    asm volatile("cp.async.cg.shared.global [%0], [%1], 16;" :: "r"(dst), "l"(src));
}
__device__ __forceinline__ void cp_commit() {
    asm volatile("cp.async.commit_group;");
}
template <int N>
__device__ __forceinline__ void cp_wait() {
    asm volatile("cp.async.wait_group %0;" :: "n"(N));
}

__device__ __forceinline__ void ldsm_x4(uint32_t r[4], uint32_t addr) {
    asm volatile("ldmatrix.sync.aligned.m8n8.x4.shared.b16 {%0,%1,%2,%3}, [%4];"
        : "=r"(r[0]), "=r"(r[1]), "=r"(r[2]), "=r"(r[3]) : "r"(addr));
}
__device__ __forceinline__ void ldsm_x2(uint32_t r[2], uint32_t addr) {
    asm volatile("ldmatrix.sync.aligned.m8n8.x2.shared.b16 {%0,%1}, [%2];"
        : "=r"(r[0]), "=r"(r[1]) : "r"(addr));
}
// fp8 e4m3 MMA with f16 accumulator
__device__ __forceinline__ void mma16832_fp8_f16(uint32_t c[2], const uint32_t a[4], const uint32_t b[2]) {
    asm volatile(
        "mma.sync.aligned.m16n8k32.row.col.f16.e4m3.e4m3.f16 "
        "{%0,%1}, {%2,%3,%4,%5}, {%6,%7}, {%0,%1};"
        : "+r"(c[0]), "+r"(c[1])
        : "r"(a[0]), "r"(a[1]), "r"(a[2]), "r"(a[3]), "r"(b[0]), "r"(b[1]));
}

// ======================= kernel 1: fp32 -> e4m3 + row norms (A and B fused) ==========
__global__ void __launch_bounds__(256) convert_norm_kernel(const float* __restrict__ srcA,
                                                           const float* __restrict__ srcB) {
    const int blk = blockIdx.x;
    const bool isB = blk >= MR;
    const int row = isB ? blk - MR : blk;
    const float* src = isB ? srcB : srcA;
    uint8_t* dst = isB ? g_B : g_A;
    float* norms = isB ? g_normS : g_normT;

    const float4* s = reinterpret_cast<const float4*>(src) + (size_t)row * (D / 4);
    uint32_t* d = reinterpret_cast<uint32_t*>(dst) + (size_t)row * (D / 4);

    float ss = 0.f;
    for (int i = threadIdx.x; i < D / 4; i += blockDim.x) {
        float4 v = s[i];
        ss = fmaf(v.x, v.x, fmaf(v.y, v.y, fmaf(v.z, v.z, fmaf(v.w, v.w, ss))));
        uint16_t lo, hi;  // e4m3x2: second f32 operand lands in byte0
        asm("cvt.rn.satfinite.e4m3x2.f32 %0, %1, %2;" : "=h"(lo) : "f"(v.y), "f"(v.x));
        asm("cvt.rn.satfinite.e4m3x2.f32 %0, %1, %2;" : "=h"(hi) : "f"(v.w), "f"(v.z));
        d[i] = (uint32_t)lo | ((uint32_t)hi << 16);
    }
    for (int o = 16; o > 0; o >>= 1) ss += __shfl_down_sync(0xFFFFFFFFu, ss, o);
    __shared__ float ws[8];
    if ((threadIdx.x & 31) == 0) ws[threadIdx.x >> 5] = ss;
    __syncthreads();
    if (threadIdx.x == 0) {
        float t = 0.f;
        #pragma unroll
        for (int w = 0; w < 8; w++) t += ws[w];
        norms[row] = sqrtf(t);
    }
}

// ======================= OTAM softmin helpers =======================
__device__ __forceinline__ float softmin2(float a, float b) {
    float m = fminf(a, b);
    float x = fabsf(a - b);
    return m - 0.1f * __logf(1.0f + __expf(-x * 10.0f));
}
__device__ __forceinline__ float softmin3(float a, float b, float c) {
    float m = fminf(fminf(a, b), c);
    float s = __expf((m - a) * 10.0f) + __expf((m - b) * 10.0f) + __expf((m - c) * 10.0f);
    return m - 0.1f * __logf(s);
}

// DP over an 8x8 dist block read from smem. TR swaps indices.
template <bool TR>
__device__ __forceinline__ float otam_dp_smem(const float* __restrict__ ds) {
    auto at = [&](int i, int j) -> float {
        return TR ? ds[j * DSTR + i] : ds[i * DSTR + j];
    };
    float prev[10], cur[10];
    prev[0] = 0.f;
    float run = 0.f;
    #pragma unroll
    for (int s = 0; s < 8; s++) {
        run += at(0, s);
        prev[s + 1] = run;
    }
    prev[9] = run;
    #pragma unroll
    for (int ll = 1; ll < 8; ll++) {
        cur[0] = 0.f;
        cur[1] = at(ll, 0) + softmin3(prev[0], prev[1], cur[0]);
        #pragma unroll
        for (int m = 2; m <= 8; m++)
            cur[m] = at(ll, m - 1) + softmin2(prev[m - 1], cur[m - 1]);
        cur[9] = softmin3(prev[8], prev[9], cur[8]);
        #pragma unroll
        for (int m = 0; m < 10; m++) prev[m] = cur[m];
    }
    return prev[9];
}

// ======================= kernel 2: FP8 GEMM + fused dist + OTAM DP =======================
__device__ __forceinline__ void load_stage(uint32_t sb, int buf, int kc, int m0, int n0, int t) {
    uint32_t a_s = sb + buf * STAGE_A;
    uint32_t b_s = sb + 2 * STAGE_A + buf * STAGE_B;
    const uint8_t* gA = g_A + (size_t)m0 * D + kc * BK;
    const uint8_t* gB = g_B + (size_t)n0 * D + kc * BK;
    #pragma unroll
    for (int i = 0; i < (BM * 8) / NTHREADS; i++) {      // 2
        int idx = i * NTHREADS + t;
        int r = idx >> 3, c = idx & 7;
        cp_async16(a_s + r * 128 + (((uint32_t)(c ^ (r & 7))) << 4),
                   gA + (size_t)r * D + c * 16);
    }
    #pragma unroll
    for (int i = 0; i < (BN * 8) / NTHREADS; i++) {      // 5
        int idx = i * NTHREADS + t;
        int r = idx >> 3, c = idx & 7;
        cp_async16(b_s + r * 128 + (((uint32_t)(c ^ (r & 7))) << 4),
                   gB + (size_t)r * D + c * 16);
    }
    cp_commit();
}

__global__ void __launch_bounds__(NTHREADS, 3) gemm_dp_kernel() {
    extern __shared__ char smem[];
    const uint32_t sb = smem_to_u32(smem);
    float* dist_s = reinterpret_cast<float*>(smem);
    const int t = threadIdx.x;
    const int l = t & 31;
    const int wid = t >> 5;
    const int wm = wid & 1;        // 2 warps over M (32 rows each)
    const int wn = wid >> 1;       // 4 warps over N (40 cols each)
    const int n0 = blockIdx.x * BN;
    const int m0 = blockIdx.y * BM;

    uint32_t acc[2][5][2];         // f16x2 accumulators, warp tile 32x40
    #pragma unroll
    for (int mt = 0; mt < 2; mt++)
        #pragma unroll
        for (int nt = 0; nt < 5; nt++) {
            acc[mt][nt][0] = 0u;
            acc[mt][nt][1] = 0u;
        }

    load_stage(sb, 0, 0, m0, n0, t);

    // per-lane ldmatrix address components (b16 view of fp8 data)
    const int la = l & 15;
    const int sa = l & 7;                 // swizzle XOR (row & 7)
    const int a_hi = l >> 4;              // which 16B half of the 32B k-step
    const int b_hi = (l >> 3) & 1;
    const uint32_t a_row_off = (uint32_t)(wm * 32 + la) * 128;
    // B x2 (single tile, lanes 0-15): row = wn*40 + nt*8 + (l&7)
    const uint32_t b_row_off = (uint32_t)(wn * 40 + sa) * 128;
    // B x4 (tile pair, all lanes): row = wn*40 + pair*16 + ((l>>4)&1)*8 + (l&7)
    const uint32_t b_row4_off = (uint32_t)(wn * 40 + ((l >> 4) & 1) * 8 + sa) * 128;

    int buf = 0;
    #pragma unroll 1
    for (int c = 0; c < NCHUNK; c++) {
        cp_wait<0>();          // chunk c's loads (this thread's) complete
        __syncthreads();       // publish chunk c; protect slot buf^1 from last reader
        if (c + 1 < NCHUNK)
            load_stage(sb, buf ^ 1, c + 1, m0, n0, t);   // overlaps compute(c)

        const uint32_t a_s = sb + buf * STAGE_A;
        const uint32_t b_s = sb + 2 * STAGE_A + buf * STAGE_B;

        #pragma unroll
        for (int ks = 0; ks < BK / 32; ks++) {   // 4 k-steps of 32 fp8
            uint32_t afr[2][4], bfr[5][2];
            #pragma unroll
            for (int mt = 0; mt < 2; mt++)
                ldsm_x4(afr[mt], a_s + a_row_off + (uint32_t)(mt * 16 * 128)
                                 + (((uint32_t)((ks * 2 + a_hi) ^ sa)) << 4));
            // B: two x4 loads cover tile pairs (0,1) and (2,3)
            #pragma unroll
            for (int p = 0; p < 2; p++) {
                uint32_t r4[4];
                ldsm_x4(r4, b_s + b_row4_off + (uint32_t)(p * 16 * 128)
                             + (((uint32_t)((ks * 2 + b_hi) ^ sa)) << 4));
                bfr[p * 2][0] = r4[0]; bfr[p * 2][1] = r4[1];
                bfr[p * 2 + 1][0] = r4[2]; bfr[p * 2 + 1][1] = r4[3];
            }
            // B tile 4: x2
            ldsm_x2(bfr[4], b_s + b_row_off + (uint32_t)(4 * 8 * 128)
                             + (((uint32_t)((ks * 2 + b_hi) ^ sa)) << 4));
            #pragma unroll
            for (int mt = 0; mt < 2; mt++)
                #pragma unroll
                for (int nt = 0; nt < 5; nt++)
                    mma16832_fp8_f16(acc[mt][nt], afr[mt], bfr[nt]);
        }
        buf ^= 1;
    }
    __syncthreads();   // all warps done with MMA before dist tile overwrites smem

    // ---- epilogue A: dist = 1 - dot/(|t||s|+eps) into smem tile ----
    const int grp = l >> 2;
    const int tid4 = l & 3;
    #pragma unroll
    for (int mt = 0; mt < 2; mt++) {
        const int lm0 = wm * 32 + mt * 16 + grp;       // local row in [0,64)
        const float nT0 = g_normT[m0 + lm0];
        const float nT1 = g_normT[m0 + lm0 + 8];
        #pragma unroll
        for (int nt = 0; nt < 5; nt++) {
            const int ln = wn * 40 + nt * 8 + tid4 * 2;  // local col in [0,160)
            const float nS0 = g_normS[n0 + ln];
            const float nS1 = g_normS[n0 + ln + 1];
            float2 lo = __half22float2(*reinterpret_cast<const __half2*>(&acc[mt][nt][0]));
            float2 hi = __half22float2(*reinterpret_cast<const __half2*>(&acc[mt][nt][1]));
            dist_s[lm0 * DSTR + ln]           = 1.f - lo.x / (nT0 * nS0 + 0.01f);
            dist_s[lm0 * DSTR + ln + 1]       = 1.f - lo.y / (nT0 * nS1 + 0.01f);
            dist_s[(lm0 + 8) * DSTR + ln]     = 1.f - hi.x / (nT1 * nS0 + 0.01f);
            dist_s[(lm0 + 8) * DSTR + ln + 1] = 1.f - hi.y / (nT1 * nS1 + 0.01f);
        }
    }
    __syncthreads();

    // ---- epilogue B: OTAM DP on 8 q-blocks x 20 sp-blocks = 160 pairs ----
    const int q0 = m0 >> 3;
    const int sp0 = n0 >> 3;
    if (t < 160) {
        const int lq = t & 7;
        const int lsp = t >> 3;
        const float* ds = dist_s + (lq * 8) * DSTR + lsp * 8;
        float v = otam_dp_smem<false>(ds) + otam_dp_smem<true>(ds);
        g_cum[(size_t)(q0 + lq) * SP + (sp0 + lsp)] = v;
    }
}

// ======================= kernel 3: per-class mean + negate =======================
// one thread per output element; class->support-index table built per block
__global__ void __launch_bounds__(512) class_reduce_kernel(const int* __restrict__ labels,
                                                           float* __restrict__ out) {
    __shared__ int idx_s[NCLS][8];
    __shared__ int cnt_s[NCLS];
    if (threadIdx.x < NCLS) cnt_s[threadIdx.x] = 0;
    __syncthreads();
    if (threadIdx.x < SP) {
        int c = labels[threadIdx.x];
        int k = atomicAdd(&cnt_s[c], 1);
        idx_s[c][k] = threadIdx.x;
    }
    __syncthreads();
    const int gid = blockIdx.x * 512 + threadIdx.x;   // Q*NCLS = 40960
    const int q = gid / NCLS;
    const int c = gid % NCLS;
    const int n = cnt_s[c];
    float s = 0.f;
    #pragma unroll 5
    for (int k = 0; k < n; k++)
        s += g_cum[(size_t)q * SP + idx_s[c][k]];
    out[gid] = -s / (float)n;
}

// ======================= launch =======================
extern "C" void kernel_launch(void* const* d_in, const int* in_sizes, int n_in,
                              void* d_out, int out_size) {
    const float* tf = (const float*)d_in[0];      // [2048, 8, 2048]
    const float* sf = (const float*)d_in[1];      // [100, 8, 2048]
    const int* labels = (const int*)d_in[2];      // [100]
    float* out = (float*)d_out;                   // [1, 2048, 20]
    (void)in_sizes; (void)n_in; (void)out_size;

    cudaFuncSetAttribute(gemm_dp_kernel,
                         cudaFuncAttributeMaxDynamicSharedMemorySize, SM_BYTES);

    convert_norm_kernel<<<MR + NR, 256>>>(tf, sf);
    gemm_dp_kernel<<<dim3(NR / BN, MR / BM), NTHREADS, SM_BYTES>>>();
    class_reduce_kernel<<<(Q * NCLS) / 512, 512>>>(labels, out);
}

// round 14
// speedup vs baseline: 1.0872x; 1.0304x over previous
#include <cuda_runtime.h>
#include <cuda_bf16.h>
#include <cuda_fp16.h>
#include <cstdint>

// ======================= problem constants =======================
static constexpr int Q    = 2048;
static constexpr int S    = 8;
static constexpr int D    = 2048;
static constexpr int SP   = 100;
static constexpr int NCLS = 20;
static constexpr int MR = Q * S;    // 16384 target frames
static constexpr int NR = SP * S;   // 800 support frames

// GEMM tiling (fp8: 1 byte/elem)
static constexpr int BM = 64;
static constexpr int BN = 160;          // 800 = 5 * 160
static constexpr int BK = 128;          // 128 fp8 = 128B row (swizzle atom)
static constexpr int NCHUNK = D / BK;   // 16
static constexpr int NTHREADS = 256;    // 8 warps: 2 over M x 4 over N

static constexpr int STAGE_A = BM * 128;   // 8192 B
static constexpr int STAGE_B = BN * 128;   // 20480 B
static constexpr int PIPE_BYTES = 2 * STAGE_A + 2 * STAGE_B;   // 57344

// epilogue dist tile in smem: [BM][DSTR] floats
static constexpr int DSTR = 164;           // 160 + pad
static constexpr int DIST_BYTES = BM * DSTR * 4;               // 41984
static constexpr int SM_BYTES = (DIST_BYTES > PIPE_BYTES) ? DIST_BYTES : PIPE_BYTES;  // 57344

// ======================= device scratch =======================
__device__ uint8_t g_A[(size_t)MR * D];            // 32 MB e4m3
__device__ uint8_t g_B[(size_t)NR * D];            // 1.6 MB e4m3
__device__ float g_normT[MR];
__device__ float g_normS[NR];
__device__ float g_cum[(size_t)Q * SP];            // [q][sp]

// ======================= asm helpers (generic-target safe) =======================
__device__ __forceinline__ uint32_t smem_to_u32(const void* smem_ptr) {
    uint32_t addr;
    asm("{ .reg .u64 tmp; cvta.to.shared.u64 tmp, %1; cvt.u32.u64 %0, tmp; }"
        : "=r"(addr) : "l"(smem_ptr));
    return addr;
}

__device__ __forceinline__ void cp_async16(uint32_t dst, const void* src) {
    asm volatile("cp.async.cg.shared.global [%0], [%1], 16;" :: "r"(dst), "l"(src));
}
__device__ __forceinline__ void cp_commit() {
    asm volatile("cp.async.commit_group;");
}
template <int N>
__device__ __forceinline__ void cp_wait() {
    asm volatile("cp.async.wait_group %0;" :: "n"(N));
}

__device__ __forceinline__ void ldsm_x4(uint32_t r[4], uint32_t addr) {
    asm volatile("ldmatrix.sync.aligned.m8n8.x4.shared.b16 {%0,%1,%2,%3}, [%4];"
        : "=r"(r[0]), "=r"(r[1]), "=r"(r[2]), "=r"(r[3]) : "r"(addr));
}
__device__ __forceinline__ void ldsm_x2(uint32_t r[2], uint32_t addr) {
    asm volatile("ldmatrix.sync.aligned.m8n8.x2.shared.b16 {%0,%1}, [%2];"
        : "=r"(r[0]), "=r"(r[1]) : "r"(addr));
}
// fp8 e4m3 MMA with f16 accumulator
__device__ __forceinline__ void mma16832_fp8_f16(uint32_t c[2], const uint32_t a[4], const uint32_t b[2]) {
    asm volatile(
        "mma.sync.aligned.m16n8k32.row.col.f16.e4m3.e4m3.f16 "
        "{%0,%1}, {%2,%3,%4,%5}, {%6,%7}, {%0,%1};"
        : "+r"(c[0]), "+r"(c[1])
        : "r"(a[0]), "r"(a[1]), "r"(a[2]), "r"(a[3]), "r"(b[0]), "r"(b[1]));
}

// ======================= kernel 1: fp32 -> e4m3 + row norms =======================
// One warp per row: 32 lanes x 16 float4 = 2048 floats. No smem, no __syncthreads.
__global__ void __launch_bounds__(256) convert_norm_kernel(const float* __restrict__ srcA,
                                                           const float* __restrict__ srcB) {
    const int warp = (blockIdx.x * 256 + threadIdx.x) >> 5;   // global warp = row index
    const int lane = threadIdx.x & 31;
    const bool isB = warp >= MR;
    const int row = isB ? warp - MR : warp;
    const float* src = isB ? srcB : srcA;
    uint8_t* dst = isB ? g_B : g_A;
    float* norms = isB ? g_normS : g_normT;

    const float4* s = reinterpret_cast<const float4*>(src) + (size_t)row * (D / 4);
    uint32_t* d = reinterpret_cast<uint32_t*>(dst) + (size_t)row * (D / 4);

    float ss = 0.f;
    #pragma unroll
    for (int b = 0; b < 4; b++) {
        float4 v[4];
        #pragma unroll
        for (int j = 0; j < 4; j++)
            v[j] = s[(b * 4 + j) * 32 + lane];
        #pragma unroll
        for (int j = 0; j < 4; j++) {
            ss = fmaf(v[j].x, v[j].x, fmaf(v[j].y, v[j].y,
                 fmaf(v[j].z, v[j].z, fmaf(v[j].w, v[j].w, ss))));
            uint16_t lo, hi;  // e4m3x2: second f32 operand lands in byte0
            asm("cvt.rn.satfinite.e4m3x2.f32 %0, %1, %2;" : "=h"(lo) : "f"(v[j].y), "f"(v[j].x));
            asm("cvt.rn.satfinite.e4m3x2.f32 %0, %1, %2;" : "=h"(hi) : "f"(v[j].w), "f"(v[j].z));
            d[(b * 4 + j) * 32 + lane] = (uint32_t)lo | ((uint32_t)hi << 16);
        }
    }
    #pragma unroll
    for (int o = 16; o > 0; o >>= 1) ss += __shfl_xor_sync(0xFFFFFFFFu, ss, o);
    if (lane == 0) norms[row] = sqrtf(ss);
}

// ======================= OTAM softmin helpers =======================
__device__ __forceinline__ float softmin2(float a, float b) {
    float m = fminf(a, b);
    float x = fabsf(a - b);
    return m - 0.1f * __logf(1.0f + __expf(-x * 10.0f));
}
__device__ __forceinline__ float softmin3(float a, float b, float c) {
    float m = fminf(fminf(a, b), c);
    float s = __expf((m - a) * 10.0f) + __expf((m - b) * 10.0f) + __expf((m - c) * 10.0f);
    return m - 0.1f * __logf(s);
}

// DP over an 8x8 dist block read from smem. TR swaps indices.
template <bool TR>
__device__ __forceinline__ float otam_dp_smem(const float* __restrict__ ds) {
    auto at = [&](int i, int j) -> float {
        return TR ? ds[j * DSTR + i] : ds[i * DSTR + j];
    };
    float prev[10], cur[10];
    prev[0] = 0.f;
    float run = 0.f;
    #pragma unroll
    for (int s = 0; s < 8; s++) {
        run += at(0, s);
        prev[s + 1] = run;
    }
    prev[9] = run;
    #pragma unroll
    for (int ll = 1; ll < 8; ll++) {
        cur[0] = 0.f;
        cur[1] = at(ll, 0) + softmin3(prev[0], prev[1], cur[0]);
        #pragma unroll
        for (int m = 2; m <= 8; m++)
            cur[m] = at(ll, m - 1) + softmin2(prev[m - 1], cur[m - 1]);
        cur[9] = softmin3(prev[8], prev[9], cur[8]);
        #pragma unroll
        for (int m = 0; m < 10; m++) prev[m] = cur[m];
    }
    return prev[9];
}

// ======================= kernel 2: FP8 GEMM + fused dist + OTAM DP =======================
__device__ __forceinline__ void load_stage(uint32_t sb, int buf, int kc, int m0, int n0, int t) {
    uint32_t a_s = sb + buf * STAGE_A;
    uint32_t b_s = sb + 2 * STAGE_A + buf * STAGE_B;
    const uint8_t* gA = g_A + (size_t)m0 * D + kc * BK;
    const uint8_t* gB = g_B + (size_t)n0 * D + kc * BK;
    #pragma unroll
    for (int i = 0; i < (BM * 8) / NTHREADS; i++) {      // 2
        int idx = i * NTHREADS + t;
        int r = idx >> 3, c = idx & 7;
        cp_async16(a_s + r * 128 + (((uint32_t)(c ^ (r & 7))) << 4),
                   gA + (size_t)r * D + c * 16);
    }
    #pragma unroll
    for (int i = 0; i < (BN * 8) / NTHREADS; i++) {      // 5
        int idx = i * NTHREADS + t;
        int r = idx >> 3, c = idx & 7;
        cp_async16(b_s + r * 128 + (((uint32_t)(c ^ (r & 7))) << 4),
                   gB + (size_t)r * D + c * 16);
    }
    cp_commit();
}

__global__ void __launch_bounds__(NTHREADS, 3) gemm_dp_kernel() {
    extern __shared__ char smem[];
    const uint32_t sb = smem_to_u32(smem);
    float* dist_s = reinterpret_cast<float*>(smem);
    const int t = threadIdx.x;
    const int l = t & 31;
    const int wid = t >> 5;
    const int wm = wid & 1;        // 2 warps over M (32 rows each)
    const int wn = wid >> 1;       // 4 warps over N (40 cols each)
    const int n0 = blockIdx.x * BN;
    const int m0 = blockIdx.y * BM;

    uint32_t acc[2][5][2];         // f16x2 accumulators, warp tile 32x40
    #pragma unroll
    for (int mt = 0; mt < 2; mt++)
        #pragma unroll
        for (int nt = 0; nt < 5; nt++) {
            acc[mt][nt][0] = 0u;
            acc[mt][nt][1] = 0u;
        }

    load_stage(sb, 0, 0, m0, n0, t);

    // per-lane ldmatrix address components (b16 view of fp8 data)
    const int la = l & 15;
    const int sa = l & 7;                 // swizzle XOR (row & 7)
    const int a_hi = l >> 4;              // which 16B half of the 32B k-step
    const int b_hi = (l >> 3) & 1;
    const uint32_t a_row_off = (uint32_t)(wm * 32 + la) * 128;
    // B x2 (single tile, lanes 0-15): row = wn*40 + nt*8 + (l&7)
    const uint32_t b_row_off = (uint32_t)(wn * 40 + sa) * 128;
    // B x4 (tile pair, all lanes): row = wn*40 + pair*16 + ((l>>4)&1)*8 + (l&7)
    const uint32_t b_row4_off = (uint32_t)(wn * 40 + ((l >> 4) & 1) * 8 + sa) * 128;

    int buf = 0;
    #pragma unroll 1
    for (int c = 0; c < NCHUNK; c++) {
        cp_wait<0>();          // chunk c's loads (this thread's) complete
        __syncthreads();       // publish chunk c; protect slot buf^1 from last reader
        if (c + 1 < NCHUNK)
            load_stage(sb, buf ^ 1, c + 1, m0, n0, t);   // overlaps compute(c)

        const uint32_t a_s = sb + buf * STAGE_A;
        const uint32_t b_s = sb + 2 * STAGE_A + buf * STAGE_B;

        #pragma unroll
        for (int ks = 0; ks < BK / 32; ks++) {   // 4 k-steps of 32 fp8
            uint32_t afr[2][4], bfr[5][2];
            #pragma unroll
            for (int mt = 0; mt < 2; mt++)
                ldsm_x4(afr[mt], a_s + a_row_off + (uint32_t)(mt * 16 * 128)
                                 + (((uint32_t)((ks * 2 + a_hi) ^ sa)) << 4));
            // B: two x4 loads cover tile pairs (0,1) and (2,3)
            #pragma unroll
            for (int p = 0; p < 2; p++) {
                uint32_t r4[4];
                ldsm_x4(r4, b_s + b_row4_off + (uint32_t)(p * 16 * 128)
                             + (((uint32_t)((ks * 2 + b_hi) ^ sa)) << 4));
                bfr[p * 2][0] = r4[0]; bfr[p * 2][1] = r4[1];
                bfr[p * 2 + 1][0] = r4[2]; bfr[p * 2 + 1][1] = r4[3];
            }
            // B tile 4: x2
            ldsm_x2(bfr[4], b_s + b_row_off + (uint32_t)(4 * 8 * 128)
                             + (((uint32_t)((ks * 2 + b_hi) ^ sa)) << 4));
            #pragma unroll
            for (int mt = 0; mt < 2; mt++)
                #pragma unroll
                for (int nt = 0; nt < 5; nt++)
                    mma16832_fp8_f16(acc[mt][nt], afr[mt], bfr[nt]);
        }
        buf ^= 1;
    }
    __syncthreads();   // all warps done with MMA before dist tile overwrites smem

    // ---- epilogue A: dist = 1 - dot/(|t||s|+eps) into smem tile ----
    const int grp = l >> 2;
    const int tid4 = l & 3;
    #pragma unroll
    for (int mt = 0; mt < 2; mt++) {
        const int lm0 = wm * 32 + mt * 16 + grp;       // local row in [0,64)
        const float nT0 = g_normT[m0 + lm0];
        const float nT1 = g_normT[m0 + lm0 + 8];
        #pragma unroll
        for (int nt = 0; nt < 5; nt++) {
            const int ln = wn * 40 + nt * 8 + tid4 * 2;  // local col in [0,160)
            const float nS0 = g_normS[n0 + ln];
            const float nS1 = g_normS[n0 + ln + 1];
            float2 lo = __half22float2(*reinterpret_cast<const __half2*>(&acc[mt][nt][0]));
            float2 hi = __half22float2(*reinterpret_cast<const __half2*>(&acc[mt][nt][1]));
            dist_s[lm0 * DSTR + ln]           = 1.f - lo.x / (nT0 * nS0 + 0.01f);
            dist_s[lm0 * DSTR + ln + 1]       = 1.f - lo.y / (nT0 * nS1 + 0.01f);
            dist_s[(lm0 + 8) * DSTR + ln]     = 1.f - hi.x / (nT1 * nS0 + 0.01f);
            dist_s[(lm0 + 8) * DSTR + ln + 1] = 1.f - hi.y / (nT1 * nS1 + 0.01f);
        }
    }
    __syncthreads();

    // ---- epilogue B: OTAM DP on 8 q-blocks x 20 sp-blocks = 160 pairs ----
    const int q0 = m0 >> 3;
    const int sp0 = n0 >> 3;
    if (t < 160) {
        const int lq = t & 7;
        const int lsp = t >> 3;
        const float* ds = dist_s + (lq * 8) * DSTR + lsp * 8;
        float v = otam_dp_smem<false>(ds) + otam_dp_smem<true>(ds);
        g_cum[(size_t)(q0 + lq) * SP + (sp0 + lsp)] = v;
    }
}

// ======================= kernel 3: per-class mean + negate =======================
// one thread per output element; class->support-index table built per block
__global__ void __launch_bounds__(512) class_reduce_kernel(const int* __restrict__ labels,
                                                           float* __restrict__ out) {
    __shared__ int idx_s[NCLS][8];
    __shared__ int cnt_s[NCLS];
    if (threadIdx.x < NCLS) cnt_s[threadIdx.x] = 0;
    __syncthreads();
    if (threadIdx.x < SP) {
        int c = labels[threadIdx.x];
        int k = atomicAdd(&cnt_s[c], 1);
        idx_s[c][k] = threadIdx.x;
    }
    __syncthreads();
    const int gid = blockIdx.x * 512 + threadIdx.x;   // Q*NCLS = 40960
    const int q = gid / NCLS;
    const int c = gid % NCLS;
    const int n = cnt_s[c];
    float s = 0.f;
    #pragma unroll 5
    for (int k = 0; k < n; k++)
        s += g_cum[(size_t)q * SP + idx_s[c][k]];
    out[gid] = -s / (float)n;
}

// ======================= launch =======================
extern "C" void kernel_launch(void* const* d_in, const int* in_sizes, int n_in,
                              void* d_out, int out_size) {
    const float* tf = (const float*)d_in[0];      // [2048, 8, 2048]
    const float* sf = (const float*)d_in[1];      // [100, 8, 2048]
    const int* labels = (const int*)d_in[2];      // [100]
    float* out = (float*)d_out;                   // [1, 2048, 20]
    (void)in_sizes; (void)n_in; (void)out_size;

    cudaFuncSetAttribute(gemm_dp_kernel,
                         cudaFuncAttributeMaxDynamicSharedMemorySize, SM_BYTES);

    convert_norm_kernel<<<(MR + NR) / 8, 256>>>(tf, sf);
    gemm_dp_kernel<<<dim3(NR / BN, MR / BM), NTHREADS, SM_BYTES>>>();
    class_reduce_kernel<<<(Q * NCLS) / 512, 512>>>(labels, out);
}

// round 15
// speedup vs baseline: 1.0962x; 1.0083x over previous
#include <cuda_runtime.h>
#include <cuda_bf16.h>
#include <cuda_fp16.h>
#include <cstdint>

// ======================= problem constants =======================
static constexpr int Q    = 2048;
static constexpr int S    = 8;
static constexpr int D    = 2048;
static constexpr int SP   = 100;
static constexpr int NCLS = 20;
static constexpr int MR = Q * S;    // 16384 target frames
static constexpr int NR = SP * S;   // 800 support frames

// GEMM tiling (fp8: 1 byte/elem)
static constexpr int BM = 64;
static constexpr int BN = 160;          // 800 = 5 * 160
static constexpr int BK = 128;          // 128 fp8 = 128B row (swizzle atom)
static constexpr int NCHUNK = D / BK;   // 16
static constexpr int NTHREADS = 256;    // 8 warps: 2 over M x 4 over N

static constexpr int STAGE_A = BM * 128;   // 8192 B
static constexpr int STAGE_B = BN * 128;   // 20480 B
static constexpr int PIPE_BYTES = 2 * STAGE_A + 2 * STAGE_B;   // 57344

// epilogue dist tile in smem: [BM][DSTR] floats
static constexpr int DSTR = 164;           // 160 + pad
static constexpr int DIST_BYTES = BM * DSTR * 4;               // 41984
static constexpr int SM_BYTES = (DIST_BYTES > PIPE_BYTES) ? DIST_BYTES : PIPE_BYTES;  // 57344

// ======================= device scratch =======================
__device__ uint8_t g_A[(size_t)MR * D];            // 32 MB e4m3
__device__ uint8_t g_B[(size_t)NR * D];            // 1.6 MB e4m3
__device__ float g_normT[MR];
__device__ float g_normS[NR];
__device__ float g_cum[(size_t)Q * SP];            // [q][sp]

// ======================= asm helpers (generic-target safe) =======================
__device__ __forceinline__ uint32_t smem_to_u32(const void* smem_ptr) {
    uint32_t addr;
    asm("{ .reg .u64 tmp; cvta.to.shared.u64 tmp, %1; cvt.u32.u64 %0, tmp; }"
        : "=r"(addr) : "l"(smem_ptr));
    return addr;
}

__device__ __forceinline__ void cp_async16(uint32_t dst, const void* src) {
    asm volatile("cp.async.cg.shared.global [%0], [%1], 16;" :: "r"(dst), "l"(src));
}
__device__ __forceinline__ void cp_commit() {
    asm volatile("cp.async.commit_group;");
}
template <int N>
__device__ __forceinline__ void cp_wait() {
    asm volatile("cp.async.wait_group %0;" :: "n"(N));
}

__device__ __forceinline__ void ldsm_x4(uint32_t r[4], uint32_t addr) {
    asm volatile("ldmatrix.sync.aligned.m8n8.x4.shared.b16 {%0,%1,%2,%3}, [%4];"
        : "=r"(r[0]), "=r"(r[1]), "=r"(r[2]), "=r"(r[3]) : "r"(addr));
}
__device__ __forceinline__ void ldsm_x2(uint32_t r[2], uint32_t addr) {
    asm volatile("ldmatrix.sync.aligned.m8n8.x2.shared.b16 {%0,%1}, [%2];"
        : "=r"(r[0]), "=r"(r[1]) : "r"(addr));
}
// fp8 e4m3 MMA with f16 accumulator
__device__ __forceinline__ void mma16832_fp8_f16(uint32_t c[2], const uint32_t a[4], const uint32_t b[2]) {
    asm volatile(
        "mma.sync.aligned.m16n8k32.row.col.f16.e4m3.e4m3.f16 "
        "{%0,%1}, {%2,%3,%4,%5}, {%6,%7}, {%0,%1};"
        : "+r"(c[0]), "+r"(c[1])
        : "r"(a[0]), "r"(a[1]), "r"(a[2]), "r"(a[3]), "r"(b[0]), "r"(b[1]));
}

// ======================= kernel 1: fp32 -> e4m3 + row norms =======================
// One warp per row: 32 lanes x 16 float4. Two batches of 8 loads (MLP=8).
__global__ void __launch_bounds__(256) convert_norm_kernel(const float* __restrict__ srcA,
                                                           const float* __restrict__ srcB) {
    const int warp = (blockIdx.x * 256 + threadIdx.x) >> 5;   // global warp = row index
    const int lane = threadIdx.x & 31;
    const bool isB = warp >= MR;
    const int row = isB ? warp - MR : warp;
    const float* src = isB ? srcB : srcA;
    uint8_t* dst = isB ? g_B : g_A;
    float* norms = isB ? g_normS : g_normT;

    const float4* s = reinterpret_cast<const float4*>(src) + (size_t)row * (D / 4);
    uint32_t* d = reinterpret_cast<uint32_t*>(dst) + (size_t)row * (D / 4);

    float ss = 0.f;
    #pragma unroll
    for (int b = 0; b < 2; b++) {
        float4 v[8];
        #pragma unroll
        for (int j = 0; j < 8; j++)
            v[j] = s[(b * 8 + j) * 32 + lane];
        #pragma unroll
        for (int j = 0; j < 8; j++) {
            ss = fmaf(v[j].x, v[j].x, fmaf(v[j].y, v[j].y,
                 fmaf(v[j].z, v[j].z, fmaf(v[j].w, v[j].w, ss))));
            uint16_t lo, hi;  // e4m3x2: second f32 operand lands in byte0
            asm("cvt.rn.satfinite.e4m3x2.f32 %0, %1, %2;" : "=h"(lo) : "f"(v[j].y), "f"(v[j].x));
            asm("cvt.rn.satfinite.e4m3x2.f32 %0, %1, %2;" : "=h"(hi) : "f"(v[j].w), "f"(v[j].z));
            d[(b * 8 + j) * 32 + lane] = (uint32_t)lo | ((uint32_t)hi << 16);
        }
    }
    #pragma unroll
    for (int o = 16; o > 0; o >>= 1) ss += __shfl_xor_sync(0xFFFFFFFFu, ss, o);
    if (lane == 0) norms[row] = sqrtf(ss);
}

// ======================= OTAM softmin helpers =======================
__device__ __forceinline__ float softmin2(float a, float b) {
    float m = fminf(a, b);
    float x = fabsf(a - b);
    return m - 0.1f * __logf(1.0f + __expf(-x * 10.0f));
}
__device__ __forceinline__ float softmin3(float a, float b, float c) {
    float m = fminf(fminf(a, b), c);
    float s = __expf((m - a) * 10.0f) + __expf((m - b) * 10.0f) + __expf((m - c) * 10.0f);
    return m - 0.1f * __logf(s);
}

// DP over an 8x8 dist block read from smem. TR swaps indices.
template <bool TR>
__device__ __forceinline__ float otam_dp_smem(const float* __restrict__ ds) {
    auto at = [&](int i, int j) -> float {
        return TR ? ds[j * DSTR + i] : ds[i * DSTR + j];
    };
    float prev[10], cur[10];
    prev[0] = 0.f;
    float run = 0.f;
    #pragma unroll
    for (int s = 0; s < 8; s++) {
        run += at(0, s);
        prev[s + 1] = run;
    }
    prev[9] = run;
    #pragma unroll
    for (int ll = 1; ll < 8; ll++) {
        cur[0] = 0.f;
        cur[1] = at(ll, 0) + softmin3(prev[0], prev[1], cur[0]);
        #pragma unroll
        for (int m = 2; m <= 8; m++)
            cur[m] = at(ll, m - 1) + softmin2(prev[m - 1], cur[m - 1]);
        cur[9] = softmin3(prev[8], prev[9], cur[8]);
        #pragma unroll
        for (int m = 0; m < 10; m++) prev[m] = cur[m];
    }
    return prev[9];
}

// ======================= kernel 2: FP8 GEMM + fused dist + OTAM DP =======================
__device__ __forceinline__ void load_stage(uint32_t sb, int buf, int kc, int m0, int n0, int t) {
    uint32_t a_s = sb + buf * STAGE_A;
    uint32_t b_s = sb + 2 * STAGE_A + buf * STAGE_B;
    const uint8_t* gA = g_A + (size_t)m0 * D + kc * BK;
    const uint8_t* gB = g_B + (size_t)n0 * D + kc * BK;
    #pragma unroll
    for (int i = 0; i < (BM * 8) / NTHREADS; i++) {      // 2
        int idx = i * NTHREADS + t;
        int r = idx >> 3, c = idx & 7;
        cp_async16(a_s + r * 128 + (((uint32_t)(c ^ (r & 7))) << 4),
                   gA + (size_t)r * D + c * 16);
    }
    #pragma unroll
    for (int i = 0; i < (BN * 8) / NTHREADS; i++) {      // 5
        int idx = i * NTHREADS + t;
        int r = idx >> 3, c = idx & 7;
        cp_async16(b_s + r * 128 + (((uint32_t)(c ^ (r & 7))) << 4),
                   gB + (size_t)r * D + c * 16);
    }
    cp_commit();
}

__global__ void __launch_bounds__(NTHREADS, 3) gemm_dp_kernel() {
    extern __shared__ char smem[];
    const uint32_t sb = smem_to_u32(smem);
    float* dist_s = reinterpret_cast<float*>(smem);
    const int t = threadIdx.x;
    const int l = t & 31;
    const int wid = t >> 5;
    const int wm = wid & 1;        // 2 warps over M (32 rows each)
    const int wn = wid >> 1;       // 4 warps over N (40 cols each)
    const int n0 = blockIdx.x * BN;
    const int m0 = blockIdx.y * BM;

    uint32_t acc[2][5][2];         // f16x2 accumulators, warp tile 32x40
    #pragma unroll
    for (int mt = 0; mt < 2; mt++)
        #pragma unroll
        for (int nt = 0; nt < 5; nt++) {
            acc[mt][nt][0] = 0u;
            acc[mt][nt][1] = 0u;
        }

    load_stage(sb, 0, 0, m0, n0, t);

    // per-lane ldmatrix address components (b16 view of fp8 data)
    const int la = l & 15;
    const int sa = l & 7;                 // swizzle XOR (row & 7)
    const int a_hi = l >> 4;              // which 16B half of the 32B k-step
    const int b_hi = (l >> 3) & 1;
    const uint32_t a_row_off = (uint32_t)(wm * 32 + la) * 128;
    // B x2 (single tile, lanes 0-15): row = wn*40 + nt*8 + (l&7)
    const uint32_t b_row_off = (uint32_t)(wn * 40 + sa) * 128;
    // B x4 (tile pair, all lanes): row = wn*40 + pair*16 + ((l>>4)&1)*8 + (l&7)
    const uint32_t b_row4_off = (uint32_t)(wn * 40 + ((l >> 4) & 1) * 8 + sa) * 128;

    int buf = 0;
    #pragma unroll 1
    for (int c = 0; c < NCHUNK; c++) {
        cp_wait<0>();          // chunk c's loads (this thread's) complete
        __syncthreads();       // publish chunk c; protect slot buf^1 from last reader
        if (c + 1 < NCHUNK)
            load_stage(sb, buf ^ 1, c + 1, m0, n0, t);   // overlaps compute(c)

        const uint32_t a_s = sb + buf * STAGE_A;
        const uint32_t b_s = sb + 2 * STAGE_A + buf * STAGE_B;

        #pragma unroll
        for (int ks = 0; ks < BK / 32; ks++) {   // 4 k-steps of 32 fp8
            uint32_t afr[2][4], bfr[5][2];
            #pragma unroll
            for (int mt = 0; mt < 2; mt++)
                ldsm_x4(afr[mt], a_s + a_row_off + (uint32_t)(mt * 16 * 128)
                                 + (((uint32_t)((ks * 2 + a_hi) ^ sa)) << 4));
            // B: two x4 loads cover tile pairs (0,1) and (2,3)
            #pragma unroll
            for (int p = 0; p < 2; p++) {
                uint32_t r4[4];
                ldsm_x4(r4, b_s + b_row4_off + (uint32_t)(p * 16 * 128)
                             + (((uint32_t)((ks * 2 + b_hi) ^ sa)) << 4));
                bfr[p * 2][0] = r4[0]; bfr[p * 2][1] = r4[1];
                bfr[p * 2 + 1][0] = r4[2]; bfr[p * 2 + 1][1] = r4[3];
            }
            // B tile 4: x2
            ldsm_x2(bfr[4], b_s + b_row_off + (uint32_t)(4 * 8 * 128)
                             + (((uint32_t)((ks * 2 + b_hi) ^ sa)) << 4));
            #pragma unroll
            for (int mt = 0; mt < 2; mt++)
                #pragma unroll
                for (int nt = 0; nt < 5; nt++)
                    mma16832_fp8_f16(acc[mt][nt], afr[mt], bfr[nt]);
        }
        buf ^= 1;
    }
    __syncthreads();   // all warps done with MMA before dist tile overwrites smem

    // ---- epilogue A: dist = 1 - dot/(|t||s|+eps) into smem tile ----
    const int grp = l >> 2;
    const int tid4 = l & 3;
    #pragma unroll
    for (int mt = 0; mt < 2; mt++) {
        const int lm0 = wm * 32 + mt * 16 + grp;       // local row in [0,64)
        const float nT0 = g_normT[m0 + lm0];
        const float nT1 = g_normT[m0 + lm0 + 8];
        #pragma unroll
        for (int nt = 0; nt < 5; nt++) {
            const int ln = wn * 40 + nt * 8 + tid4 * 2;  // local col in [0,160)
            const float nS0 = g_normS[n0 + ln];
            const float nS1 = g_normS[n0 + ln + 1];
            float2 lo = __half22float2(*reinterpret_cast<const __half2*>(&acc[mt][nt][0]));
            float2 hi = __half22float2(*reinterpret_cast<const __half2*>(&acc[mt][nt][1]));
            dist_s[lm0 * DSTR + ln]           = 1.f - lo.x / (nT0 * nS0 + 0.01f);
            dist_s[lm0 * DSTR + ln + 1]       = 1.f - lo.y / (nT0 * nS1 + 0.01f);
            dist_s[(lm0 + 8) * DSTR + ln]     = 1.f - hi.x / (nT1 * nS0 + 0.01f);
            dist_s[(lm0 + 8) * DSTR + ln + 1] = 1.f - hi.y / (nT1 * nS1 + 0.01f);
        }
    }
    __syncthreads();

    // ---- epilogue B: OTAM DP on 8 q-blocks x 20 sp-blocks = 160 pairs ----
    const int q0 = m0 >> 3;
    const int sp0 = n0 >> 3;
    if (t < 160) {
        const int lq = t & 7;
        const int lsp = t >> 3;
        const float* ds = dist_s + (lq * 8) * DSTR + lsp * 8;
        float v = otam_dp_smem<false>(ds) + otam_dp_smem<true>(ds);
        g_cum[(size_t)(q0 + lq) * SP + (sp0 + lsp)] = v;
    }
}

// ======================= kernel 3: per-class mean + negate =======================
// one thread per output element; 128-thread blocks for full-chip spread
__global__ void __launch_bounds__(128) class_reduce_kernel(const int* __restrict__ labels,
                                                           float* __restrict__ out) {
    __shared__ int idx_s[NCLS][8];
    __shared__ int cnt_s[NCLS];
    if (threadIdx.x < NCLS) cnt_s[threadIdx.x] = 0;
    __syncthreads();
    if (threadIdx.x < SP) {
        int c = labels[threadIdx.x];
        int k = atomicAdd(&cnt_s[c], 1);
        idx_s[c][k] = threadIdx.x;
    }
    __syncthreads();
    const int gid = blockIdx.x * 128 + threadIdx.x;   // Q*NCLS = 40960
    const int q = gid / NCLS;
    const int c = gid % NCLS;
    const int n = cnt_s[c];
    float s = 0.f;
    #pragma unroll 5
    for (int k = 0; k < n; k++)
        s += g_cum[(size_t)q * SP + idx_s[c][k]];
    out[gid] = -s / (float)n;
}

// ======================= launch =======================
extern "C" void kernel_launch(void* const* d_in, const int* in_sizes, int n_in,
                              void* d_out, int out_size) {
    const float* tf = (const float*)d_in[0];      // [2048, 8, 2048]
    const float* sf = (const float*)d_in[1];      // [100, 8, 2048]
    const int* labels = (const int*)d_in[2];      // [100]
    float* out = (float*)d_out;                   // [1, 2048, 20]
    (void)in_sizes; (void)n_in; (void)out_size;

    cudaFuncSetAttribute(gemm_dp_kernel,
                         cudaFuncAttributeMaxDynamicSharedMemorySize, SM_BYTES);

    convert_norm_kernel<<<(MR + NR) / 8, 256>>>(tf, sf);
    gemm_dp_kernel<<<dim3(NR / BN, MR / BM), NTHREADS, SM_BYTES>>>();
    class_reduce_kernel<<<(Q * NCLS) / 128, 128>>>(labels, out);
}